// round 2
// baseline (speedup 1.0000x reference)
#include <cuda_runtime.h>
#include <cstdint>

// Problem constants
#define BB 8
#define NN 4096
#define KK 26
#define DD 64

// Stage-1 tiling
#define NCHUNK 64                 // n-chunks per batch
#define CHUNK_N (NN / NCHUNK)     // 64 n's per block
#define KD (KK * DD)              // 1664

// Deterministic partial-sum scratch: [B][NCHUNK][K][D] = 3.4 MB
__device__ float g_partial[BB * NCHUNK * KD];

// ---------- packed fp32x2 helpers (sm_100a; ptxas never emits these from C++) ----
typedef unsigned long long u64;

__device__ __forceinline__ u64 ffma2(u64 a, u64 b, u64 c) {
    u64 d;
    asm("fma.rn.f32x2 %0, %1, %2, %3;" : "=l"(d) : "l"(a), "l"(b), "l"(c));
    return d;
}
__device__ __forceinline__ u64 fmul2(u64 a, u64 b) {
    u64 d;
    asm("mul.rn.f32x2 %0, %1, %2;" : "=l"(d) : "l"(a), "l"(b));
    return d;
}
__device__ __forceinline__ u64 pack2(float x) {
    u64 r;
    asm("mov.b64 %0, {%1, %1};" : "=l"(r) : "f"(x));
    return r;
}

// Stage 1: stream neighbors/targets/a for one (batch, n-chunk), accumulate
// per-(k,d) partials in registers (packed f32x2), write tile to g_partial.
// Thread map: d4 = tid & 15 (float4 group over D=64), kl = tid >> 4 (0..15).
// Each thread owns k = kl and k = kl + 16 (second valid only for kl < 10).
__global__ void __launch_bounds__(256, 4) gat_stage1(
    const float* __restrict__ targets,     // (B,N,D)
    const float* __restrict__ neighbors,   // (B,N,K,D)
    const float* __restrict__ aw,          // (B,N,K)
    const float* __restrict__ kt,          // kernel_target (D)
    const float* __restrict__ bt,          // bias_target   (D)
    const float* __restrict__ kn,          // kernel_neighbor (D)
    const float* __restrict__ bn)          // bias_neighbor   (D)
{
    const int chunk = blockIdx.x;          // 0..NCHUNK-1
    const int b     = blockIdx.y;          // 0..B-1
    const int tid   = threadIdx.x;
    const int d4    = tid & 15;
    const int kl    = tid >> 4;
    const bool has_k1 = (kl + 16) < KK;    // kl < 10

    // Loop-invariant per-d constants as packed f32x2 pairs
    const ulonglong2 kt2 = ((const ulonglong2*)kt)[d4];
    const ulonglong2 bt2 = ((const ulonglong2*)bt)[d4];
    const ulonglong2 kn2 = ((const ulonglong2*)kn)[d4];
    const ulonglong2 bn2 = ((const ulonglong2*)bn)[d4];

    u64 acc0x = 0, acc0y = 0, acc1x = 0, acc1y = 0;
    {
        // zero-init packed accumulators (bit pattern 0 == {0.f,0.f})
    }

    const long n0 = (long)chunk * CHUNK_N;
    const long row0 = (long)b * NN + n0;

    const float* tg_base = targets   + row0 * DD;
    const float* nb_base = neighbors + row0 * (long)KD;
    const float* aw_base = aw        + row0 * KK;

    #pragma unroll 4
    for (int i = 0; i < CHUNK_N; i++) {
        const float* nrow = nb_base + (long)i * KD;
        const float* arow = aw_base + (long)i * KK;

        // Issue all loads for this n up front (MLP)
        ulonglong2 tg = ((const ulonglong2*)(tg_base + (long)i * DD))[d4];
        float a0 = __ldg(arow + kl);
        ulonglong2 nb0 = ((const ulonglong2*)(nrow + kl * DD))[d4];
        float a1 = 0.f;
        ulonglong2 nb1 = make_ulonglong2(0, 0);
        if (has_k1) {
            a1  = __ldg(arow + kl + 16);
            nb1 = ((const ulonglong2*)(nrow + (kl + 16) * DD))[d4];
        }

        // t = targets * kernel_neighbor + bias_neighbor
        u64 ttx = ffma2(tg.x, kn2.x, bn2.x);
        u64 tty = ffma2(tg.y, kn2.y, bn2.y);

        // k = kl : acc += (nb*kt+bt) * (t*a)
        {
            u64 pa = pack2(a0);
            u64 tax = fmul2(ttx, pa);
            u64 tay = fmul2(tty, pa);
            u64 nvx = ffma2(nb0.x, kt2.x, bt2.x);
            u64 nvy = ffma2(nb0.y, kt2.y, bt2.y);
            acc0x = ffma2(nvx, tax, acc0x);
            acc0y = ffma2(nvy, tay, acc0y);
        }
        // k = kl + 16
        if (has_k1) {
            u64 pa = pack2(a1);
            u64 tax = fmul2(ttx, pa);
            u64 tay = fmul2(tty, pa);
            u64 nvx = ffma2(nb1.x, kt2.x, bt2.x);
            u64 nvy = ffma2(nb1.y, kt2.y, bt2.y);
            acc1x = ffma2(nvx, tax, acc1x);
            acc1y = ffma2(nvy, tay, acc1y);
        }
    }

    float* outp = g_partial + ((long)(b * NCHUNK + chunk)) * KD;
    ((ulonglong2*)(outp + kl * DD))[d4] = make_ulonglong2(acc0x, acc0y);
    if (has_k1)
        ((ulonglong2*)(outp + (kl + 16) * DD))[d4] = make_ulonglong2(acc1x, acc1y);
}

// Stage 2: one block per (b,k). 256 threads = 64 d-lanes x 4 chunk-groups.
// Each thread sums 16 chunks (coalesced: consecutive d contiguous), smem tree,
// sigmoid, write.
__global__ void __launch_bounds__(256) gat_stage2(float* __restrict__ out)
{
    __shared__ float red[4][DD];

    const int k = blockIdx.x;              // 0..KK-1
    const int b = blockIdx.y;              // 0..BB-1
    const int tid = threadIdx.x;
    const int d = tid & (DD - 1);
    const int g = tid >> 6;                // 0..3

    // g_partial[(b*NCHUNK + c)*KK + k][d]
    const float* base = g_partial + ((long)(b * NCHUNK) * KK + k) * DD + d;
    const long cstride = (long)KK * DD;    // per-chunk stride

    float s = 0.f;
    #pragma unroll
    for (int j = 0; j < NCHUNK / 4; j++) {  // 16 chunks per group
        int c = g * (NCHUNK / 4) + j;
        s += base[(long)c * cstride];
    }
    red[g][d] = s;
    __syncthreads();

    if (tid < DD) {
        float t = red[0][d] + red[1][d] + red[2][d] + red[3][d];
        float r = 1.0f / (1.0f + __expf(-t));
        out[((long)b * KK + k) * DD + d] = r;
    }
}

extern "C" void kernel_launch(void* const* d_in, const int* in_sizes, int n_in,
                              void* d_out, int out_size)
{
    const float* targets   = (const float*)d_in[0];  // (B,N,D)
    const float* neighbors = (const float*)d_in[1];  // (B,N,K,D)
    const float* aw        = (const float*)d_in[2];  // (B,N,K)
    const float* kt        = (const float*)d_in[3];  // kernel_target
    const float* bt        = (const float*)d_in[4];  // bias_target
    const float* kn        = (const float*)d_in[5];  // kernel_neighbor
    const float* bn        = (const float*)d_in[6];  // bias_neighbor
    float* out             = (float*)d_out;          // (1,B,K,D)

    (void)in_sizes; (void)n_in; (void)out_size;

    dim3 g1(NCHUNK, BB);
    gat_stage1<<<g1, 256>>>(targets, neighbors, aw, kt, bt, kn, bn);

    dim3 g2(KK, BB);
    gat_stage2<<<g2, 256>>>(out);
}

// round 3
// speedup vs baseline: 1.0523x; 1.0523x over previous
#include <cuda_runtime.h>

// Problem constants
#define BB 8
#define NN 4096
#define KK 26
#define DD 64

// Stage-1 tiling
#define NCHUNK 128                // n-chunks per batch
#define CHUNK_N (NN / NCHUNK)     // 32 n's per block
#define KD (KK * DD)              // 1664

// Deterministic partial-sum scratch: [B][NCHUNK][K][D] = 6.8 MB
__device__ float g_partial[BB * NCHUNK * KD];

__device__ __forceinline__ float4 f4_fma(float4 x, float4 m, float4 b) {
    float4 r;
    r.x = fmaf(x.x, m.x, b.x);
    r.y = fmaf(x.y, m.y, b.y);
    r.z = fmaf(x.z, m.z, b.z);
    r.w = fmaf(x.w, m.w, b.w);
    return r;
}

__device__ __forceinline__ float4 f4_scale(float4 x, float s) {
    float4 r; r.x = x.x * s; r.y = x.y * s; r.z = x.z * s; r.w = x.w * s;
    return r;
}

// acc += u * v
__device__ __forceinline__ void f4_fma_acc(float4& acc, float4 u, float4 v) {
    acc.x = fmaf(u.x, v.x, acc.x);
    acc.y = fmaf(u.y, v.y, acc.y);
    acc.z = fmaf(u.z, v.z, acc.z);
    acc.w = fmaf(u.w, v.w, acc.w);
}

// Stage 1: stream neighbors/targets/a for one (batch, n-chunk), accumulate
// per-(k,d) partials in registers, write partial tile to g_partial.
// Thread map: d4 = tid & 15 (float4 group over D=64), kl = tid >> 4 (0..15).
// Each thread owns k = kl and k = kl + 16 (second valid only for kl < 10).
__global__ void __launch_bounds__(256, 4) gat_stage1(
    const float* __restrict__ targets,     // (B,N,D)
    const float* __restrict__ neighbors,   // (B,N,K,D)
    const float* __restrict__ aw,          // (B,N,K)
    const float* __restrict__ kt,          // kernel_target (D)
    const float* __restrict__ bt,          // bias_target   (D)
    const float* __restrict__ kn,          // kernel_neighbor (D)
    const float* __restrict__ bn)          // bias_neighbor   (D)
{
    const int chunk = blockIdx.x;          // 0..NCHUNK-1
    const int b     = blockIdx.y;          // 0..B-1
    const int tid   = threadIdx.x;
    const int d4    = tid & 15;
    const int kl    = tid >> 4;
    const bool has_k1 = (kl + 16) < KK;    // kl < 10

    // Loop-invariant per-d constants
    const float4 kt4 = ((const float4*)kt)[d4];
    const float4 bt4 = ((const float4*)bt)[d4];
    const float4 kn4 = ((const float4*)kn)[d4];
    const float4 bn4 = ((const float4*)bn)[d4];

    float4 acc0 = make_float4(0.f, 0.f, 0.f, 0.f);
    float4 acc1 = make_float4(0.f, 0.f, 0.f, 0.f);

    const long n0 = (long)chunk * CHUNK_N;
    const long row0 = (long)b * NN + n0;

    const float* tg_base = targets   + row0 * DD;
    const float* nb_base = neighbors + row0 * (long)KD;
    const float* aw_base = aw        + row0 * KK;

    #pragma unroll 4
    for (int i = 0; i < CHUNK_N; i++) {
        // t[b,n,:] = targets * kernel_neighbor + bias_neighbor
        float4 tg = ((const float4*)(tg_base + (long)i * DD))[d4];
        float4 tt = f4_fma(tg, kn4, bn4);

        const float* nrow = nb_base + (long)i * KD;
        const float* arow = aw_base + (long)i * KK;

        // k = kl
        {
            float a0 = __ldg(arow + kl);
            float4 nb = ((const float4*)(nrow + kl * DD))[d4];
            float4 nv = f4_fma(nb, kt4, bt4);        // neighbors*kt + bt
            f4_fma_acc(acc0, nv, f4_scale(tt, a0));  // acc += nv * (tt*a)
        }
        // k = kl + 16
        if (has_k1) {
            float a1 = __ldg(arow + kl + 16);
            float4 nb = ((const float4*)(nrow + (kl + 16) * DD))[d4];
            float4 nv = f4_fma(nb, kt4, bt4);
            f4_fma_acc(acc1, nv, f4_scale(tt, a1));
        }
    }

    float* outp = g_partial + ((long)(b * NCHUNK + chunk)) * KD;
    ((float4*)(outp + kl * DD))[d4] = acc0;
    if (has_k1) ((float4*)(outp + (kl + 16) * DD))[d4] = acc1;
}

// Stage 2: one block per (b,k). 512 threads = 64 d-lanes x 8 chunk-groups.
// Each thread sums 16 chunks (independent, unrolled, coalesced over d),
// smem tree over the 8 groups, sigmoid, write.
__global__ void __launch_bounds__(512) gat_stage2(float* __restrict__ out)
{
    __shared__ float red[8][DD];

    const int k = blockIdx.x;              // 0..KK-1
    const int b = blockIdx.y;              // 0..BB-1
    const int tid = threadIdx.x;
    const int d = tid & (DD - 1);
    const int g = tid >> 6;                // 0..7

    // g_partial[((b*NCHUNK + c)*KK + k)*DD + d]
    const float* base = g_partial + ((long)(b * NCHUNK) * KK + k) * DD + d;
    const long cstride = (long)KK * DD;    // per-chunk stride

    float s = 0.f;
    #pragma unroll
    for (int j = 0; j < NCHUNK / 8; j++) { // 16 chunks per group
        int c = g * (NCHUNK / 8) + j;
        s += base[(long)c * cstride];
    }
    red[g][d] = s;
    __syncthreads();

    if (tid < DD) {
        float t = 0.f;
        #pragma unroll
        for (int gg = 0; gg < 8; gg++) t += red[gg][d];
        float r = 1.0f / (1.0f + __expf(-t));
        out[((long)b * KK + k) * DD + d] = r;
    }
}

extern "C" void kernel_launch(void* const* d_in, const int* in_sizes, int n_in,
                              void* d_out, int out_size)
{
    const float* targets   = (const float*)d_in[0];  // (B,N,D)
    const float* neighbors = (const float*)d_in[1];  // (B,N,K,D)
    const float* aw        = (const float*)d_in[2];  // (B,N,K)
    const float* kt        = (const float*)d_in[3];  // kernel_target
    const float* bt        = (const float*)d_in[4];  // bias_target
    const float* kn        = (const float*)d_in[5];  // kernel_neighbor
    const float* bn        = (const float*)d_in[6];  // bias_neighbor
    float* out             = (float*)d_out;          // (1,B,K,D)

    (void)in_sizes; (void)n_in; (void)out_size;

    dim3 g1(NCHUNK, BB);
    gat_stage1<<<g1, 256>>>(targets, neighbors, aw, kt, bt, kn, bn);

    dim3 g2(KK, BB);
    gat_stage2<<<g2, 512>>>(out);
}